// round 13
// baseline (speedup 1.0000x reference)
#include <cuda_runtime.h>
#include <stdint.h>

// KANLayer: BATCH=512, NUM_IN=NUM_OUT=128, SIZE=16384, K=3, G=5 (8 coefs)
// Outputs: y[512,128], pre.T[512,16384], psp.T[512,16384], pac.T[512,16384]
// R11: (1) y zeroed inside kan_basis (memset node removed)
//      (2) BB=2 batch passes per block reuse the staged 22.5KB table chunk
//          (halves table L2 traffic), grid stays 1024
//      (3) bulk stores issued before atomics; pass-2 smem reuse guarded

#define NUM_IN   128
#define SIZE_T   16384
#define BATCH    512
#define SCHUNK   512                  // s per block (4 o-rows x 128 i)
#define OCHUNK   (SCHUNK / NUM_IN)    // 4
#define BTILE    8                    // batches per pass
#define BB       2                    // passes per block
#define BQ       4                    // batches per thread per pass
#define THREADS  256
#define NCHUNK   (SIZE_T / SCHUNK)    // 32
#define NBGRP    (BATCH / (BTILE * BB))  // 32

// dynamic smem layout (bytes)
#define OFF_COEF 0
#define OFF_SB   (SCHUNK * 32)                    // 16384
#define OFF_SS   (OFF_SB + SCHUNK * 4)            // 18432
#define OFF_MK   (OFF_SS + SCHUNK * 4)            // 20480
#define OFF_PSP  (OFF_MK + SCHUNK * 4)            // 22528
#define OFF_PAC  (OFF_PSP + BTILE * SCHUNK * 4)   // 38912
#define OFF_BAR  (OFF_PAC + BTILE * SCHUNK * 4)   // 55296
#define SMEM_TOTAL (OFF_BAR + 16)
#define STAGE_BYTES (OFF_PSP)                     // tables: 22528

__device__ float g_basis[BATCH * NUM_IN * 8];
__device__ float g_sl[BATCH * NUM_IN];

__device__ __forceinline__ uint32_t smem_u32(const void* p)
{
    uint32_t a;
    asm("{ .reg .u64 t; cvta.to.shared.u64 t, %1; cvt.u32.u64 %0, t; }"
        : "=r"(a) : "l"(p));
    return a;
}

__device__ __forceinline__ void bulk_g2s(uint32_t dst, const void* src,
                                         uint32_t bytes, uint32_t bar)
{
    asm volatile(
        "cp.async.bulk.shared::cta.global.mbarrier::complete_tx::bytes "
        "[%0], [%1], %2, [%3];"
        :: "r"(dst), "l"(src), "r"(bytes), "r"(bar) : "memory");
}

__device__ __forceinline__ void bulk_s2g(void* dst, uint32_t src, uint32_t bytes)
{
    asm volatile(
        "cp.async.bulk.global.shared::cta.bulk_group [%0], [%1], %2;"
        :: "l"(dst), "r"(src), "r"(bytes) : "memory");
}

// Degree-3 Cox-de-Boor on a uniform grid (division-free; knots are a tiled
// linspace so all denominators are p*h).
__device__ __forceinline__ void basis8(float xv, const float* __restrict__ g,
                                       float* __restrict__ Bv)
{
    float e[12];
    const float h = (g[5] - g[0]) * 0.2f;
    e[3] = g[0]; e[4] = g[1]; e[5] = g[2]; e[6] = g[3]; e[7] = g[4]; e[8] = g[5];
    e[2] = g[0] - h;  e[1] = g[0] - 2.0f * h;  e[0] = g[0] - 3.0f * h;
    e[9] = g[5] + h;  e[10] = g[5] + 2.0f * h; e[11] = g[5] + 3.0f * h;
    const float rh = __frcp_rn(h);

    float B[11];
#pragma unroll
    for (int j = 0; j < 11; j++)
        B[j] = (xv >= e[j] && xv < e[j + 1]) ? 1.0f : 0.0f;

#pragma unroll
    for (int p = 1; p <= 3; p++) {
        const float rhp = rh * (p == 1 ? 1.0f : (p == 2 ? 0.5f : (1.0f / 3.0f)));
#pragma unroll
        for (int j = 0; j + p < 11; j++) {
            B[j] = (xv - e[j]) * rhp * B[j] + (e[j + p + 1] - xv) * rhp * B[j + 1];
        }
    }
#pragma unroll
    for (int j = 0; j < 8; j++) Bv[j] = B[j];
}

// Kernel 1: basis + silu per unique (b,i), once; also zero-inits y.
extern "C" __global__ void __launch_bounds__(256)
kan_basis(const float* __restrict__ x, const float* __restrict__ knots,
          float* __restrict__ y)
{
    const int idx = blockIdx.x * 256 + threadIdx.x;   // (b,i) pair
    const int i = idx & (NUM_IN - 1);

    y[idx] = 0.0f;                                    // replaces memset node

    float gl[6];
    const float* g = knots + (size_t)i * 6;
#pragma unroll
    for (int m = 0; m < 6; m++) gl[m] = __ldg(g + m);

    const float xv = __ldg(x + idx);
    float Bv[8];
    basis8(xv, gl, Bv);

    float4* bp = (float4*)(g_basis + (size_t)idx * 8);
    bp[0] = make_float4(Bv[0], Bv[1], Bv[2], Bv[3]);
    bp[1] = make_float4(Bv[4], Bv[5], Bv[6], Bv[7]);
    g_sl[idx] = xv / (1.0f + __expf(-xv));
}

// Kernel 2: main
extern "C" __global__ void __launch_bounds__(THREADS, 4)
kan_main(const float* __restrict__ x,
         const float* __restrict__ scale_b,
         const float* __restrict__ scale_sp,
         const float* __restrict__ coef,
         const float* __restrict__ mask,
         float* __restrict__ y,
         float* __restrict__ pre,
         float* __restrict__ psp,
         float* __restrict__ pac)
{
    extern __shared__ char smem[];
    float4* s_coef = (float4*)(smem + OFF_COEF);
    float*  s_sb   = (float*)(smem + OFF_SB);
    float*  s_ss   = (float*)(smem + OFF_SS);
    float*  s_mk   = (float*)(smem + OFF_MK);
    float*  s_psp  = (float*)(smem + OFF_PSP);
    float*  s_pac  = (float*)(smem + OFF_PAC);
    const uint32_t bar = smem_u32(smem + OFF_BAR);

    const int bg    = blockIdx.x >> 5;      // 32 batch groups (16 batches)
    const int chunk = blockIdx.x & 31;      // 32 s-chunks
    const int sbase = chunk * SCHUNK;

    const int tid  = threadIdx.x;
    const int i    = tid & (NUM_IN - 1);
    const int slot = tid >> 7;              // 0 / 1

    if (tid == 0) {
        asm volatile("mbarrier.init.shared::cta.b64 [%0], 1;" :: "r"(bar) : "memory");
    }
    __syncthreads();
    if (tid == 0) {
        asm volatile("mbarrier.arrive.expect_tx.shared::cta.b64 _, [%0], %1;"
                     :: "r"(bar), "r"((uint32_t)STAGE_BYTES) : "memory");
        bulk_g2s(smem_u32(s_coef), coef + (size_t)sbase * 8, SCHUNK * 32, bar);
        bulk_g2s(smem_u32(s_sb),   scale_b  + sbase, SCHUNK * 4, bar);
        bulk_g2s(smem_u32(s_ss),   scale_sp + sbase, SCHUNK * 4, bar);
        bulk_g2s(smem_u32(s_mk),   mask     + sbase, SCHUNK * 4, bar);
    }

#pragma unroll
    for (int bb = 0; bb < BB; bb++) {
        const int bbase = bg * (BTILE * BB) + bb * BTILE;
        const int b0    = bbase + slot * BQ;

        // ---- load precomputed basis/silu (overlaps staging / drain) ----
        float4 B0[BQ], B1[BQ];
        float xv[BQ], sl[BQ], acc[BQ];
#pragma unroll
        for (int q = 0; q < BQ; q++) {
            const int bi = (b0 + q) * NUM_IN + i;
            const float4* bp = (const float4*)(g_basis + (size_t)bi * 8);
            B0[q] = __ldg(bp);
            B1[q] = __ldg(bp + 1);
            xv[q] = __ldg(x + bi);
            sl[q] = __ldg(g_sl + bi);
            acc[q] = 0.0f;
        }

        if (bb == 0) {
            // wait for staged tables
            asm volatile(
                "{\n\t"
                ".reg .pred P;\n\t"
                "W%=:\n\t"
                "mbarrier.try_wait.parity.acquire.cta.shared::cta.b64 P, [%0], 0;\n\t"
                "@!P bra W%=;\n\t"
                "}"
                :: "r"(bar) : "memory");
        } else {
            // pass-1 bulk stores must finish reading s_psp/s_pac before reuse
            if (tid < BTILE)
                asm volatile("cp.async.bulk.wait_group.read 0;" ::: "memory");
            __syncthreads();
        }

        // base already includes +i; o-loop adds o*NUM_IN only
        float* p0 = pre + (size_t)b0 * SIZE_T + (size_t)sbase + i;

        // ---- main loop: 4 o-rows x 4 batches per thread ----
#pragma unroll
        for (int o = 0; o < OCHUNK; o++) {
            const int    rl  = o * NUM_IN + i;
            const int    off = o * NUM_IN;
            const float4 cA  = s_coef[rl * 2];
            const float4 cB  = s_coef[rl * 2 + 1];
            const float  m   = s_mk[rl];
            const float  sbv = s_sb[rl];
            const float  ssv = s_ss[rl];
#pragma unroll
            for (int q = 0; q < BQ; q++) {
                const float sp = (cA.x * B0[q].x + cA.y * B0[q].y
                                + cA.z * B0[q].z + cA.w * B0[q].w
                                + cB.x * B1[q].x + cB.y * B1[q].y
                                + cB.z * B1[q].z + cB.w * B1[q].w) * m;
                const float pa = sbv * sl[q] + ssv * sp;
                const int sm = (slot * BQ + q) * SCHUNK + rl;
                s_psp[sm] = sp;
                s_pac[sm] = pa;
                p0[(size_t)q * SIZE_T + off] = xv[q];
                acc[q] += pa;
            }
        }

        __syncthreads();

        // ---- async bulk stores first, then overlap atomics with drain ----
        if (tid < BTILE) {
            asm volatile("fence.proxy.async.shared::cta;" ::: "memory");
            const size_t go = (size_t)(bbase + tid) * SIZE_T + sbase;
            bulk_s2g(psp + go, smem_u32(s_psp + tid * SCHUNK), SCHUNK * 4);
            bulk_s2g(pac + go, smem_u32(s_pac + tid * SCHUNK), SCHUNK * 4);
            asm volatile("cp.async.bulk.commit_group;" ::: "memory");
        }

#pragma unroll
        for (int q = 0; q < BQ; q++)
            atomicAdd(y + (size_t)(b0 + q) * NUM_IN + i, acc[q]);
    }

    // final drain before CTA exit (smem dealloc)
    if (tid < BTILE)
        asm volatile("cp.async.bulk.wait_group 0;" ::: "memory");
}

extern "C" void kernel_launch(void* const* d_in, const int* in_sizes, int n_in,
                              void* d_out, int out_size)
{
    const float* x    = (const float*)d_in[0];
    const float* sb   = (const float*)d_in[1];
    const float* ss   = (const float*)d_in[2];
    const float* coef = (const float*)d_in[3];
    const float* mask = (const float*)d_in[4];
    const float* kn   = (const float*)d_in[5];

    float* y   = (float*)d_out;
    float* pre = y   + (size_t)BATCH * NUM_IN;
    float* psp = pre + (size_t)BATCH * SIZE_T;
    float* pac = psp + (size_t)BATCH * SIZE_T;

    cudaFuncSetAttribute(kan_main, cudaFuncAttributeMaxDynamicSharedMemorySize,
                         SMEM_TOTAL);

    kan_basis<<<BATCH * NUM_IN / 256, 256>>>(x, kn, y);
    kan_main<<<NBGRP * NCHUNK, THREADS, SMEM_TOTAL>>>(x, sb, ss, coef, mask,
                                                      y, pre, psp, pac);
}

// round 16
// speedup vs baseline: 1.0836x; 1.0836x over previous
#include <cuda_runtime.h>
#include <stdint.h>

// KANLayer: BATCH=512, NUM_IN=NUM_OUT=128, SIZE=16384, K=3, G=5 (8 coefs)
// Outputs: y[512,128], pre.T[512,16384], psp.T[512,16384], pac.T[512,16384]
// R14: R10 single-pass structure, but BTILE 8->16 via THREADS 512 (halves
// table L2 re-reads with NO serialization), y zeroed in kan_basis.

#define NUM_IN   128
#define SIZE_T   16384
#define BATCH    512
#define SCHUNK   512                  // s per block (4 o-rows x 128 i)
#define OCHUNK   (SCHUNK / NUM_IN)    // 4
#define BTILE    16                   // batches per block
#define BQ       4                    // batches per thread
#define THREADS  512
#define NCHUNK   (SIZE_T / SCHUNK)    // 32
#define NBGRP    (BATCH / BTILE)      // 32

// dynamic smem layout (bytes)
#define OFF_COEF 0
#define OFF_SB   (SCHUNK * 32)                    // 16384
#define OFF_SS   (OFF_SB + SCHUNK * 4)            // 18432
#define OFF_MK   (OFF_SS + SCHUNK * 4)            // 20480
#define OFF_PSP  (OFF_MK + SCHUNK * 4)            // 22528
#define OFF_PAC  (OFF_PSP + BTILE * SCHUNK * 4)   // 55296
#define OFF_BAR  (OFF_PAC + BTILE * SCHUNK * 4)   // 88064
#define SMEM_TOTAL (OFF_BAR + 16)
#define STAGE_BYTES (OFF_PSP)                     // tables: 22528

__device__ float g_basis[BATCH * NUM_IN * 8];
__device__ float g_sl[BATCH * NUM_IN];

__device__ __forceinline__ uint32_t smem_u32(const void* p)
{
    uint32_t a;
    asm("{ .reg .u64 t; cvta.to.shared.u64 t, %1; cvt.u32.u64 %0, t; }"
        : "=r"(a) : "l"(p));
    return a;
}

__device__ __forceinline__ void bulk_g2s(uint32_t dst, const void* src,
                                         uint32_t bytes, uint32_t bar)
{
    asm volatile(
        "cp.async.bulk.shared::cta.global.mbarrier::complete_tx::bytes "
        "[%0], [%1], %2, [%3];"
        :: "r"(dst), "l"(src), "r"(bytes), "r"(bar) : "memory");
}

__device__ __forceinline__ void bulk_s2g(void* dst, uint32_t src, uint32_t bytes)
{
    asm volatile(
        "cp.async.bulk.global.shared::cta.bulk_group [%0], [%1], %2;"
        :: "l"(dst), "r"(src), "r"(bytes) : "memory");
}

// Degree-3 Cox-de-Boor on a uniform grid (division-free; knots are a tiled
// linspace so all denominators are p*h).
__device__ __forceinline__ void basis8(float xv, const float* __restrict__ g,
                                       float* __restrict__ Bv)
{
    float e[12];
    const float h = (g[5] - g[0]) * 0.2f;
    e[3] = g[0]; e[4] = g[1]; e[5] = g[2]; e[6] = g[3]; e[7] = g[4]; e[8] = g[5];
    e[2] = g[0] - h;  e[1] = g[0] - 2.0f * h;  e[0] = g[0] - 3.0f * h;
    e[9] = g[5] + h;  e[10] = g[5] + 2.0f * h; e[11] = g[5] + 3.0f * h;
    const float rh = __frcp_rn(h);

    float B[11];
#pragma unroll
    for (int j = 0; j < 11; j++)
        B[j] = (xv >= e[j] && xv < e[j + 1]) ? 1.0f : 0.0f;

#pragma unroll
    for (int p = 1; p <= 3; p++) {
        const float rhp = rh * (p == 1 ? 1.0f : (p == 2 ? 0.5f : (1.0f / 3.0f)));
#pragma unroll
        for (int j = 0; j + p < 11; j++) {
            B[j] = (xv - e[j]) * rhp * B[j] + (e[j + p + 1] - xv) * rhp * B[j + 1];
        }
    }
#pragma unroll
    for (int j = 0; j < 8; j++) Bv[j] = B[j];
}

// Kernel 1: basis + silu per unique (b,i), once; also zero-inits y.
extern "C" __global__ void __launch_bounds__(256)
kan_basis(const float* __restrict__ x, const float* __restrict__ knots,
          float* __restrict__ y)
{
    const int idx = blockIdx.x * 256 + threadIdx.x;   // (b,i) pair
    const int i = idx & (NUM_IN - 1);

    y[idx] = 0.0f;                                    // replaces memset node

    float gl[6];
    const float* g = knots + (size_t)i * 6;
#pragma unroll
    for (int m = 0; m < 6; m++) gl[m] = __ldg(g + m);

    const float xv = __ldg(x + idx);
    float Bv[8];
    basis8(xv, gl, Bv);

    float4* bp = (float4*)(g_basis + (size_t)idx * 8);
    bp[0] = make_float4(Bv[0], Bv[1], Bv[2], Bv[3]);
    bp[1] = make_float4(Bv[4], Bv[5], Bv[6], Bv[7]);
    g_sl[idx] = xv / (1.0f + __expf(-xv));
}

// Kernel 2: main
extern "C" __global__ void __launch_bounds__(THREADS, 2)
kan_main(const float* __restrict__ x,
         const float* __restrict__ scale_b,
         const float* __restrict__ scale_sp,
         const float* __restrict__ coef,
         const float* __restrict__ mask,
         float* __restrict__ y,
         float* __restrict__ pre,
         float* __restrict__ psp,
         float* __restrict__ pac)
{
    extern __shared__ char smem[];
    float4* s_coef = (float4*)(smem + OFF_COEF);
    float*  s_sb   = (float*)(smem + OFF_SB);
    float*  s_ss   = (float*)(smem + OFF_SS);
    float*  s_mk   = (float*)(smem + OFF_MK);
    float*  s_psp  = (float*)(smem + OFF_PSP);
    float*  s_pac  = (float*)(smem + OFF_PAC);
    const uint32_t bar = smem_u32(smem + OFF_BAR);

    const int bg    = blockIdx.x >> 5;      // 32 batch groups (16 batches)
    const int chunk = blockIdx.x & 31;      // 32 s-chunks
    const int sbase = chunk * SCHUNK;
    const int bbase = bg * BTILE;

    const int tid  = threadIdx.x;
    const int i    = tid & (NUM_IN - 1);
    const int slot = tid >> 7;              // 0..3
    const int b0   = bbase + slot * BQ;

    if (tid == 0) {
        asm volatile("mbarrier.init.shared::cta.b64 [%0], 1;" :: "r"(bar) : "memory");
    }
    __syncthreads();
    if (tid == 0) {
        asm volatile("mbarrier.arrive.expect_tx.shared::cta.b64 _, [%0], %1;"
                     :: "r"(bar), "r"((uint32_t)STAGE_BYTES) : "memory");
        bulk_g2s(smem_u32(s_coef), coef + (size_t)sbase * 8, SCHUNK * 32, bar);
        bulk_g2s(smem_u32(s_sb),   scale_b  + sbase, SCHUNK * 4, bar);
        bulk_g2s(smem_u32(s_ss),   scale_sp + sbase, SCHUNK * 4, bar);
        bulk_g2s(smem_u32(s_mk),   mask     + sbase, SCHUNK * 4, bar);
    }

    // ---- load precomputed basis/silu while bulk copy is in flight ----
    float4 B0[BQ], B1[BQ];
    float xv[BQ], sl[BQ], acc[BQ];
#pragma unroll
    for (int q = 0; q < BQ; q++) {
        const int bi = (b0 + q) * NUM_IN + i;
        const float4* bp = (const float4*)(g_basis + (size_t)bi * 8);
        B0[q] = __ldg(bp);
        B1[q] = __ldg(bp + 1);
        xv[q] = __ldg(x + bi);
        sl[q] = __ldg(g_sl + bi);
        acc[q] = 0.0f;
    }

    // wait for staged tables
    asm volatile(
        "{\n\t"
        ".reg .pred P;\n\t"
        "W%=:\n\t"
        "mbarrier.try_wait.parity.acquire.cta.shared::cta.b64 P, [%0], 0;\n\t"
        "@!P bra W%=;\n\t"
        "}"
        :: "r"(bar) : "memory");

    // base already includes +i; o-loop adds o*NUM_IN only
    float* p0 = pre + (size_t)b0 * SIZE_T + (size_t)sbase + i;

    // ---- main loop: 4 o-rows x 4 batches per thread ----
#pragma unroll
    for (int o = 0; o < OCHUNK; o++) {
        const int    rl  = o * NUM_IN + i;
        const int    off = o * NUM_IN;
        const float4 cA  = s_coef[rl * 2];
        const float4 cB  = s_coef[rl * 2 + 1];
        const float  m   = s_mk[rl];
        const float  sbv = s_sb[rl];
        const float  ssv = s_ss[rl];
#pragma unroll
        for (int q = 0; q < BQ; q++) {
            const float sp = (cA.x * B0[q].x + cA.y * B0[q].y
                            + cA.z * B0[q].z + cA.w * B0[q].w
                            + cB.x * B1[q].x + cB.y * B1[q].y
                            + cB.z * B1[q].z + cB.w * B1[q].w) * m;
            const float pa = sbv * sl[q] + ssv * sp;
            const int sm = (slot * BQ + q) * SCHUNK + rl;
            s_psp[sm] = sp;
            s_pac[sm] = pa;
            p0[(size_t)q * SIZE_T + off] = xv[q];
            acc[q] += pa;
        }
    }

    __syncthreads();

    // ---- async bulk stores first, then overlap atomics with the drain ----
    if (tid < BTILE) {
        asm volatile("fence.proxy.async.shared::cta;" ::: "memory");
        const size_t go = (size_t)(bbase + tid) * SIZE_T + sbase;
        bulk_s2g(psp + go, smem_u32(s_psp + tid * SCHUNK), SCHUNK * 4);
        bulk_s2g(pac + go, smem_u32(s_pac + tid * SCHUNK), SCHUNK * 4);
        asm volatile("cp.async.bulk.commit_group;" ::: "memory");
    }

    // ---- y[b,i] partial reduction ----
#pragma unroll
    for (int q = 0; q < BQ; q++)
        atomicAdd(y + (size_t)(b0 + q) * NUM_IN + i, acc[q]);

    // final drain before CTA exit (smem dealloc)
    if (tid < BTILE)
        asm volatile("cp.async.bulk.wait_group 0;" ::: "memory");
}

extern "C" void kernel_launch(void* const* d_in, const int* in_sizes, int n_in,
                              void* d_out, int out_size)
{
    const float* x    = (const float*)d_in[0];
    const float* sb   = (const float*)d_in[1];
    const float* ss   = (const float*)d_in[2];
    const float* coef = (const float*)d_in[3];
    const float* mask = (const float*)d_in[4];
    const float* kn   = (const float*)d_in[5];

    float* y   = (float*)d_out;
    float* pre = y   + (size_t)BATCH * NUM_IN;
    float* psp = pre + (size_t)BATCH * SIZE_T;
    float* pac = psp + (size_t)BATCH * SIZE_T;

    cudaFuncSetAttribute(kan_main, cudaFuncAttributeMaxDynamicSharedMemorySize,
                         SMEM_TOTAL);

    kan_basis<<<BATCH * NUM_IN / 256, 256>>>(x, kn, y);
    kan_main<<<NBGRP * NCHUNK, THREADS, SMEM_TOTAL>>>(x, sb, ss, coef, mask,
                                                      y, pre, psp, pac);
}

// round 17
// speedup vs baseline: 1.0862x; 1.0024x over previous
#include <cuda_runtime.h>
#include <stdint.h>

// KANLayer: BATCH=512, NUM_IN=NUM_OUT=128, SIZE=16384, K=3, G=5 (8 coefs)
// Outputs: y[512,128], pre.T[512,16384], psp.T[512,16384], pac.T[512,16384]
// R17 = R14 + PDL: kan_main launches programmatically-dependent on kan_basis,
// overlapping the basis kernel + launch gap with kan_main's TMA table staging.

#define NUM_IN   128
#define SIZE_T   16384
#define BATCH    512
#define SCHUNK   512                  // s per block (4 o-rows x 128 i)
#define OCHUNK   (SCHUNK / NUM_IN)    // 4
#define BTILE    16                   // batches per block
#define BQ       4                    // batches per thread
#define THREADS  512
#define NCHUNK   (SIZE_T / SCHUNK)    // 32
#define NBGRP    (BATCH / BTILE)      // 32

// dynamic smem layout (bytes)
#define OFF_COEF 0
#define OFF_SB   (SCHUNK * 32)                    // 16384
#define OFF_SS   (OFF_SB + SCHUNK * 4)            // 18432
#define OFF_MK   (OFF_SS + SCHUNK * 4)            // 20480
#define OFF_PSP  (OFF_MK + SCHUNK * 4)            // 22528
#define OFF_PAC  (OFF_PSP + BTILE * SCHUNK * 4)   // 55296
#define OFF_BAR  (OFF_PAC + BTILE * SCHUNK * 4)   // 88064
#define SMEM_TOTAL (OFF_BAR + 16)
#define STAGE_BYTES (OFF_PSP)                     // tables: 22528

__device__ float g_basis[BATCH * NUM_IN * 8];
__device__ float g_sl[BATCH * NUM_IN];

__device__ __forceinline__ uint32_t smem_u32(const void* p)
{
    uint32_t a;
    asm("{ .reg .u64 t; cvta.to.shared.u64 t, %1; cvt.u32.u64 %0, t; }"
        : "=r"(a) : "l"(p));
    return a;
}

__device__ __forceinline__ void bulk_g2s(uint32_t dst, const void* src,
                                         uint32_t bytes, uint32_t bar)
{
    asm volatile(
        "cp.async.bulk.shared::cta.global.mbarrier::complete_tx::bytes "
        "[%0], [%1], %2, [%3];"
        :: "r"(dst), "l"(src), "r"(bytes), "r"(bar) : "memory");
}

__device__ __forceinline__ void bulk_s2g(void* dst, uint32_t src, uint32_t bytes)
{
    asm volatile(
        "cp.async.bulk.global.shared::cta.bulk_group [%0], [%1], %2;"
        :: "l"(dst), "r"(src), "r"(bytes) : "memory");
}

// Degree-3 Cox-de-Boor on a uniform grid (division-free; knots are a tiled
// linspace so all denominators are p*h).
__device__ __forceinline__ void basis8(float xv, const float* __restrict__ g,
                                       float* __restrict__ Bv)
{
    float e[12];
    const float h = (g[5] - g[0]) * 0.2f;
    e[3] = g[0]; e[4] = g[1]; e[5] = g[2]; e[6] = g[3]; e[7] = g[4]; e[8] = g[5];
    e[2] = g[0] - h;  e[1] = g[0] - 2.0f * h;  e[0] = g[0] - 3.0f * h;
    e[9] = g[5] + h;  e[10] = g[5] + 2.0f * h; e[11] = g[5] + 3.0f * h;
    const float rh = __frcp_rn(h);

    float B[11];
#pragma unroll
    for (int j = 0; j < 11; j++)
        B[j] = (xv >= e[j] && xv < e[j + 1]) ? 1.0f : 0.0f;

#pragma unroll
    for (int p = 1; p <= 3; p++) {
        const float rhp = rh * (p == 1 ? 1.0f : (p == 2 ? 0.5f : (1.0f / 3.0f)));
#pragma unroll
        for (int j = 0; j + p < 11; j++) {
            B[j] = (xv - e[j]) * rhp * B[j] + (e[j + p + 1] - xv) * rhp * B[j + 1];
        }
    }
#pragma unroll
    for (int j = 0; j < 8; j++) Bv[j] = B[j];
}

// Kernel 1: basis + silu per unique (b,i), once; also zero-inits y.
extern "C" __global__ void __launch_bounds__(256)
kan_basis(const float* __restrict__ x, const float* __restrict__ knots,
          float* __restrict__ y)
{
    const int idx = blockIdx.x * 256 + threadIdx.x;   // (b,i) pair
    const int i = idx & (NUM_IN - 1);

    y[idx] = 0.0f;                                    // replaces memset node

    float gl[6];
    const float* g = knots + (size_t)i * 6;
#pragma unroll
    for (int m = 0; m < 6; m++) gl[m] = __ldg(g + m);

    const float xv = __ldg(x + idx);
    float Bv[8];
    basis8(xv, gl, Bv);

    float4* bp = (float4*)(g_basis + (size_t)idx * 8);
    bp[0] = make_float4(Bv[0], Bv[1], Bv[2], Bv[3]);
    bp[1] = make_float4(Bv[4], Bv[5], Bv[6], Bv[7]);
    g_sl[idx] = xv / (1.0f + __expf(-xv));

    // allow the dependent kan_main grid to launch
    cudaTriggerProgrammaticLaunchCompletion();
}

// Kernel 2: main
extern "C" __global__ void __launch_bounds__(THREADS, 2)
kan_main(const float* __restrict__ x,
         const float* __restrict__ scale_b,
         const float* __restrict__ scale_sp,
         const float* __restrict__ coef,
         const float* __restrict__ mask,
         float* __restrict__ y,
         float* __restrict__ pre,
         float* __restrict__ psp,
         float* __restrict__ pac)
{
    extern __shared__ char smem[];
    float4* s_coef = (float4*)(smem + OFF_COEF);
    float*  s_sb   = (float*)(smem + OFF_SB);
    float*  s_ss   = (float*)(smem + OFF_SS);
    float*  s_mk   = (float*)(smem + OFF_MK);
    float*  s_psp  = (float*)(smem + OFF_PSP);
    float*  s_pac  = (float*)(smem + OFF_PAC);
    const uint32_t bar = smem_u32(smem + OFF_BAR);

    const int bg    = blockIdx.x >> 5;      // 32 batch groups (16 batches)
    const int chunk = blockIdx.x & 31;      // 32 s-chunks
    const int sbase = chunk * SCHUNK;
    const int bbase = bg * BTILE;

    const int tid  = threadIdx.x;
    const int i    = tid & (NUM_IN - 1);
    const int slot = tid >> 7;              // 0..3
    const int b0   = bbase + slot * BQ;

    // ---- basis-independent preamble: runs BEFORE kan_basis completes ----
    if (tid == 0) {
        asm volatile("mbarrier.init.shared::cta.b64 [%0], 1;" :: "r"(bar) : "memory");
    }
    __syncthreads();
    if (tid == 0) {
        asm volatile("mbarrier.arrive.expect_tx.shared::cta.b64 _, [%0], %1;"
                     :: "r"(bar), "r"((uint32_t)STAGE_BYTES) : "memory");
        bulk_g2s(smem_u32(s_coef), coef + (size_t)sbase * 8, SCHUNK * 32, bar);
        bulk_g2s(smem_u32(s_sb),   scale_b  + sbase, SCHUNK * 4, bar);
        bulk_g2s(smem_u32(s_ss),   scale_sp + sbase, SCHUNK * 4, bar);
        bulk_g2s(smem_u32(s_mk),   mask     + sbase, SCHUNK * 4, bar);
    }

    // wait for kan_basis results (g_basis, g_sl, y=0) to be visible
    cudaGridDependencySynchronize();

    // ---- load precomputed basis/silu while bulk copy is in flight ----
    float4 B0[BQ], B1[BQ];
    float xv[BQ], sl[BQ], acc[BQ];
#pragma unroll
    for (int q = 0; q < BQ; q++) {
        const int bi = (b0 + q) * NUM_IN + i;
        const float4* bp = (const float4*)(g_basis + (size_t)bi * 8);
        B0[q] = __ldg(bp);
        B1[q] = __ldg(bp + 1);
        xv[q] = __ldg(x + bi);
        sl[q] = __ldg(g_sl + bi);
        acc[q] = 0.0f;
    }

    // wait for staged tables
    asm volatile(
        "{\n\t"
        ".reg .pred P;\n\t"
        "W%=:\n\t"
        "mbarrier.try_wait.parity.acquire.cta.shared::cta.b64 P, [%0], 0;\n\t"
        "@!P bra W%=;\n\t"
        "}"
        :: "r"(bar) : "memory");

    // base already includes +i; o-loop adds o*NUM_IN only
    float* p0 = pre + (size_t)b0 * SIZE_T + (size_t)sbase + i;

    // ---- main loop: 4 o-rows x 4 batches per thread ----
#pragma unroll
    for (int o = 0; o < OCHUNK; o++) {
        const int    rl  = o * NUM_IN + i;
        const int    off = o * NUM_IN;
        const float4 cA  = s_coef[rl * 2];
        const float4 cB  = s_coef[rl * 2 + 1];
        const float  m   = s_mk[rl];
        const float  sbv = s_sb[rl];
        const float  ssv = s_ss[rl];
#pragma unroll
        for (int q = 0; q < BQ; q++) {
            const float sp = (cA.x * B0[q].x + cA.y * B0[q].y
                            + cA.z * B0[q].z + cA.w * B0[q].w
                            + cB.x * B1[q].x + cB.y * B1[q].y
                            + cB.z * B1[q].z + cB.w * B1[q].w) * m;
            const float pa = sbv * sl[q] + ssv * sp;
            const int sm = (slot * BQ + q) * SCHUNK + rl;
            s_psp[sm] = sp;
            s_pac[sm] = pa;
            p0[(size_t)q * SIZE_T + off] = xv[q];
            acc[q] += pa;
        }
    }

    __syncthreads();

    // ---- async bulk stores first, then overlap atomics with the drain ----
    if (tid < BTILE) {
        asm volatile("fence.proxy.async.shared::cta;" ::: "memory");
        const size_t go = (size_t)(bbase + tid) * SIZE_T + sbase;
        bulk_s2g(psp + go, smem_u32(s_psp + tid * SCHUNK), SCHUNK * 4);
        bulk_s2g(pac + go, smem_u32(s_pac + tid * SCHUNK), SCHUNK * 4);
        asm volatile("cp.async.bulk.commit_group;" ::: "memory");
    }

    // ---- y[b,i] partial reduction ----
#pragma unroll
    for (int q = 0; q < BQ; q++)
        atomicAdd(y + (size_t)(b0 + q) * NUM_IN + i, acc[q]);

    // final drain before CTA exit (smem dealloc)
    if (tid < BTILE)
        asm volatile("cp.async.bulk.wait_group 0;" ::: "memory");
}

extern "C" void kernel_launch(void* const* d_in, const int* in_sizes, int n_in,
                              void* d_out, int out_size)
{
    const float* x    = (const float*)d_in[0];
    const float* sb   = (const float*)d_in[1];
    const float* ss   = (const float*)d_in[2];
    const float* coef = (const float*)d_in[3];
    const float* mask = (const float*)d_in[4];
    const float* kn   = (const float*)d_in[5];

    float* y   = (float*)d_out;
    float* pre = y   + (size_t)BATCH * NUM_IN;
    float* psp = pre + (size_t)BATCH * SIZE_T;
    float* pac = psp + (size_t)BATCH * SIZE_T;

    cudaFuncSetAttribute(kan_main, cudaFuncAttributeMaxDynamicSharedMemorySize,
                         SMEM_TOTAL);

    kan_basis<<<BATCH * NUM_IN / 256, 256>>>(x, kn, y);

    // kan_main with programmatic dependent launch on kan_basis
    cudaLaunchConfig_t cfg = {};
    cfg.gridDim = dim3(NBGRP * NCHUNK);
    cfg.blockDim = dim3(THREADS);
    cfg.dynamicSmemBytes = SMEM_TOTAL;
    cfg.stream = 0;
    cudaLaunchAttribute attrs[1];
    attrs[0].id = cudaLaunchAttributeProgrammaticStreamSerialization;
    attrs[0].val.programmaticStreamSerializationAllowed = 1;
    cfg.attrs = attrs;
    cfg.numAttrs = 1;
    cudaLaunchKernelEx(&cfg, kan_main, x, sb, ss, coef, mask,
                       y, pre, psp, pac);
}